// round 9
// baseline (speedup 1.0000x reference)
#include <cuda_runtime.h>
#include <cuda_fp16.h>
#include <cstdint>

#define T_TOK 8192
#define HID   1536
#define NEXP  32
#define TOPK  8
#define INTER 512
#define N1    (2*INTER)       // 1024
#define MAXP  (T_TOK*TOPK)    // 65536

#define KSLAB 64
#define STG   49152           // Ah16K + Bh32K
#define SMEMG (1024 + 4*STG)  // 197632

// ---------------- device scratch ----------------
__device__ int   g_counts[NEXP];
__device__ int   g_list[NEXP * T_TOK];
__device__ float g_pairw[MAXP];
__device__ __half g_xh[(size_t)T_TOK * HID];
__device__ __half g_w13h[(size_t)NEXP * N1 * HID];
__device__ __half g_w2h[(size_t)NEXP * HID * INTER];
__device__ __half g_hh[(size_t)MAXP * INTER];
__device__ float g_y[(size_t)MAXP * HID];

// ---------------- PTX helpers (sm_103-baseline safe) ----------------
__device__ __forceinline__ uint32_t smem_u32(const void* p) {
    uint32_t a;
    asm("{ .reg .u64 t; cvta.to.shared.u64 t, %1; cvt.u32.u64 %0, t; }" : "=r"(a) : "l"(p));
    return a;
}
__device__ __forceinline__ uint32_t swz(uint32_t b) { return b ^ ((b >> 3) & 0x70); }

__device__ __forceinline__ void cp16(uint32_t dst, const void* src, bool valid) {
    int sz = valid ? 16 : 0;
    asm volatile("cp.async.cg.shared.global [%0], [%1], 16, %2;\n" :: "r"(dst), "l"(src), "r"(sz));
}
__device__ __forceinline__ void cp_commit() { asm volatile("cp.async.commit_group;" ::: "memory"); }
template <int N> __device__ __forceinline__ void cp_wait() {
    asm volatile("cp.async.wait_group %0;" :: "n"(N) : "memory");
}
__device__ __forceinline__ void ldsm4(uint32_t* r, uint32_t addr) {
    asm volatile("ldmatrix.sync.aligned.m8n8.x4.shared.b16 {%0,%1,%2,%3}, [%4];"
                 : "=r"(r[0]), "=r"(r[1]), "=r"(r[2]), "=r"(r[3]) : "r"(addr));
}
// fp16-accumulate HMMA: D(f16x2 x2) = A*B + C(f16)
__device__ __forceinline__ void mma_h16(uint32_t* c, const uint32_t* a, const uint32_t* b) {
    asm volatile("mma.sync.aligned.m16n8k16.row.col.f16.f16.f16.f16 "
                 "{%0,%1}, {%2,%3,%4,%5}, {%6,%7}, {%0,%1};"
                 : "+r"(c[0]), "+r"(c[1])
                 : "r"(a[0]), "r"(a[1]), "r"(a[2]), "r"(a[3]), "r"(b[0]), "r"(b[1]));
}

// flush fp16 fragment accumulators into fp32 masters, zero the fp16 side
__device__ __forceinline__ void flush_acc(uint32_t facc[4][8][2], float acc[4][8][4]) {
    #pragma unroll
    for (int m = 0; m < 4; m++)
        #pragma unroll
        for (int n = 0; n < 8; n++) {
            float2 lo = __half22float2(*reinterpret_cast<__half2*>(&facc[m][n][0]));
            float2 hi = __half22float2(*reinterpret_cast<__half2*>(&facc[m][n][1]));
            acc[m][n][0] += lo.x; acc[m][n][1] += lo.y;
            acc[m][n][2] += hi.x; acc[m][n][3] += hi.y;
            facc[m][n][0] = 0u;   facc[m][n][1] = 0u;
        }
}

// ---------------- reset ----------------
__global__ void reset_kernel() {
    if (threadIdx.x < NEXP) g_counts[threadIdx.x] = 0;
}

// ---------------- fp32 -> fp16 (hi only) ----------------
__device__ __forceinline__ void cvt_hi(const float4* __restrict__ src, uint2* __restrict__ hi, int n4) {
    int i = blockIdx.x * blockDim.x + threadIdx.x;
    if (i >= n4) return;
    float4 v = src[i];
    __half h0 = __float2half_rn(v.x), h1 = __float2half_rn(v.y);
    __half h2 = __float2half_rn(v.z), h3 = __float2half_rn(v.w);
    uint2 hv;
    hv.x = (uint32_t)*reinterpret_cast<unsigned short*>(&h0) | ((uint32_t)*reinterpret_cast<unsigned short*>(&h1) << 16);
    hv.y = (uint32_t)*reinterpret_cast<unsigned short*>(&h2) | ((uint32_t)*reinterpret_cast<unsigned short*>(&h3) << 16);
    hi[i] = hv;
}
__global__ void cvt_x_kernel(const float* __restrict__ x) {
    cvt_hi((const float4*)x, (uint2*)g_xh, T_TOK * HID / 4);
}
__global__ void cvt_w13_kernel(const float* __restrict__ w) {
    cvt_hi((const float4*)w, (uint2*)g_w13h, NEXP * N1 * HID / 4);
}
__global__ void cvt_w2_kernel(const float* __restrict__ w) {
    cvt_hi((const float4*)w, (uint2*)g_w2h, NEXP * HID * INTER / 4);
}

// ---------------- Router: one warp per token (fp32, exact) ----------------
__global__ __launch_bounds__(256) void router_kernel(const float* __restrict__ x,
                                                     const float* __restrict__ gw) {
    const unsigned FULL = 0xffffffffu;
    int warp = (blockIdx.x * blockDim.x + threadIdx.x) >> 5;
    int lane = threadIdx.x & 31;
    if (warp >= T_TOK) return;
    const int t = warp;
    const float4* x4 = (const float4*)(x + (size_t)t * HID);

    float logit = 0.f;
    for (int e = 0; e < NEXP; e++) {
        const float4* g4 = (const float4*)(gw + (size_t)e * HID);
        float s = 0.f;
        for (int k = lane; k < HID / 4; k += 32) {
            float4 a = x4[k], b = g4[k];
            s += a.x * b.x + a.y * b.y + a.z * b.z + a.w * b.w;
        }
        #pragma unroll
        for (int off = 16; off; off >>= 1) s += __shfl_xor_sync(FULL, s, off);
        if (lane == e) logit = s;
    }
    float m = logit;
    #pragma unroll
    for (int off = 16; off; off >>= 1) m = fmaxf(m, __shfl_xor_sync(FULL, m, off));
    float p = expf(logit - m);
    float sum = p;
    #pragma unroll
    for (int off = 16; off; off >>= 1) sum += __shfl_xor_sync(FULL, sum, off);
    p = p / sum;

    float keep = p, topsum = 0.f;
    int myslot = -1;
    for (int s = 0; s < TOPK; s++) {
        float v = keep; int bl = lane;
        #pragma unroll
        for (int off = 16; off; off >>= 1) {
            float ov = __shfl_down_sync(FULL, v, off);
            int   ol = __shfl_down_sync(FULL, bl, off);
            if (ov > v || (ov == v && ol < bl)) { v = ov; bl = ol; }
        }
        bl = __shfl_sync(FULL, bl, 0);
        v  = __shfl_sync(FULL, v, 0);
        topsum += v;
        if (lane == bl) { myslot = s; keep = -1.f; }
    }
    if (myslot >= 0) {
        int pos = atomicAdd(&g_counts[lane], 1);
        g_list[lane * T_TOK + pos] = t * TOPK + myslot;
        g_pairw[t * TOPK + myslot] = p / topsum;
    }
}

// ================= GEMM1: x(fp16) @ w13(fp16)^T, fp16-acc + fp32 flush, fused SiLU =================
// CTA 128(M) x 256(N=128 gate + 128 up), K-slab 64, 4-stage, SW128 (128B rows).
// Warp grid 2x4, warp tile 64x64. Stage: Ah[0,16K) Bh[16K,48K). Flush every 2 slabs (K=128).
__global__ __launch_bounds__(256, 1) void gemm1_mma() {
    const int e  = blockIdx.z;
    const int M  = g_counts[e];
    const int m0 = blockIdx.y * 128;
    if (m0 >= M) return;
    const int t = blockIdx.x;   // 0..3

    extern __shared__ char dsm[];
    int* s_pair = (int*)dsm;
    const uint32_t TILE = smem_u32(dsm) + 1024;
    float* sC = (float*)(dsm + 1024);

    const int tid = threadIdx.x, wid = tid >> 5, lane = tid & 31;
    const int warp_m = wid >> 2, warp_n = wid & 3;

    if (tid < 128) {
        int gr = m0 + tid;
        s_pair[tid] = (gr < M) ? g_list[e * T_TOK + gr] : -1;
    }
    __syncthreads();

    uint32_t offA[4], dstA[4]; bool vA[4];
    uint32_t offB[8], dstB[8];
    #pragma unroll
    for (int i = 0; i < 4; i++) {
        int c = tid + i * 256, r = c >> 3, cw = c & 7;
        int p = s_pair[r];
        vA[i] = (p >= 0);
        offA[i] = (uint32_t)(vA[i] ? (p >> 3) : 0) * HID + cw * 8;
        dstA[i] = swz(r * 128 + cw * 16);
    }
    #pragma unroll
    for (int i = 0; i < 8; i++) {
        int c = tid + i * 256, r = c >> 3, cw = c & 7;
        int brow = (r < 128) ? (t * 128 + r) : (512 + t * 128 + (r - 128));
        offB[i] = ((uint32_t)e * N1 + brow) * HID + cw * 8;
        dstB[i] = swz(r * 128 + cw * 16);
    }

    auto load_stage = [&](int b, int k0) {
        uint32_t st = TILE + b * STG;
        #pragma unroll
        for (int i = 0; i < 4; i++)
            cp16(st + dstA[i], g_xh + offA[i] + k0, vA[i]);
        #pragma unroll
        for (int i = 0; i < 8; i++)
            cp16(st + 16384 + dstB[i], g_w13h + offB[i] + k0, true);
        cp_commit();
    };

    float acc[4][8][4];
    uint32_t facc[4][8][2];
    #pragma unroll
    for (int m = 0; m < 4; m++)
        #pragma unroll
        for (int n = 0; n < 8; n++) {
            acc[m][n][0] = acc[m][n][1] = acc[m][n][2] = acc[m][n][3] = 0.f;
            facc[m][n][0] = facc[m][n][1] = 0u;
        }

    const uint32_t a_row = warp_m * 64 + (lane & 15);
    const uint32_t a_kb  = (lane >> 4) * 16;
    const uint32_t b_row = warp_n * 64 + (lane & 7) + ((lane >> 4) << 3);
    const uint32_t b_kb  = ((lane >> 3) & 1) * 16;

    const int S = HID / KSLAB;  // 24
    load_stage(0, 0);
    load_stage(1, KSLAB);
    load_stage(2, 2 * KSLAB);
    for (int s = 0; s < S; s++) {
        if (s + 2 < S) cp_wait<2>(); else if (s + 1 < S) cp_wait<1>(); else cp_wait<0>();
        __syncthreads();
        if (s + 3 < S) load_stage((s + 3) & 3, (s + 3) * KSLAB);
        const uint32_t st = TILE + (s & 3) * STG;
        const uint32_t sAh = st, sBh = st + 16384;
        #pragma unroll
        for (int ks = 0; ks < 4; ks++) {
            uint32_t ah[4][4];
            #pragma unroll
            for (int m = 0; m < 4; m++) {
                uint32_t off = (a_row + m * 16) * 128 + ks * 32 + a_kb;
                ldsm4(ah[m], sAh + swz(off));
            }
            #pragma unroll
            for (int j = 0; j < 4; j++) {
                uint32_t off = (b_row + j * 16) * 128 + ks * 32 + b_kb;
                uint32_t th[4];
                ldsm4(th, sBh + swz(off));
                #pragma unroll
                for (int m = 0; m < 4; m++) {
                    mma_h16(facc[m][2*j],   ah[m], th);
                    mma_h16(facc[m][2*j+1], ah[m], th + 2);
                }
            }
        }
        if (s & 1) flush_acc(facc, acc);
    }
    __syncthreads();

    // ---- fused epilogue: gate warps (warp_n<2) stage C via smem; up warps emit fp16 h ----
    const int g = lane >> 2, tg = lane & 3;
    if (warp_n < 2) {
        #pragma unroll
        for (int m = 0; m < 4; m++) {
            int row = warp_m * 64 + m * 16 + g;
            #pragma unroll
            for (int n = 0; n < 8; n++) {
                int col = warp_n * 64 + n * 8 + tg * 2;
                sC[row * 132 + col]           = acc[m][n][0];
                sC[row * 132 + col + 1]       = acc[m][n][1];
                sC[(row + 8) * 132 + col]     = acc[m][n][2];
                sC[(row + 8) * 132 + col + 1] = acc[m][n][3];
            }
        }
    }
    __syncthreads();
    if (warp_n >= 2) {
        #pragma unroll
        for (int m = 0; m < 4; m++) {
            int row = warp_m * 64 + m * 16 + g;
            int p0 = s_pair[row], p1 = s_pair[row + 8];
            #pragma unroll
            for (int n = 0; n < 8; n++) {
                int ucol = (warp_n - 2) * 64 + n * 8 + tg * 2;
                if (p0 >= 0) {
                    float g0 = sC[row * 132 + ucol], g1 = sC[row * 132 + ucol + 1];
                    float h0 = g0 / (1.f + expf(-g0)) * acc[m][n][0];
                    float h1 = g1 / (1.f + expf(-g1)) * acc[m][n][1];
                    __half b0 = __float2half_rn(h0), b1 = __float2half_rn(h1);
                    uint32_t o = ((uint32_t)p0 * INTER + t * 128 + ucol) >> 1;
                    ((uint32_t*)g_hh)[o] = (uint32_t)*reinterpret_cast<unsigned short*>(&b0) |
                                           ((uint32_t)*reinterpret_cast<unsigned short*>(&b1) << 16);
                }
                if (p1 >= 0) {
                    float g0 = sC[(row + 8) * 132 + ucol], g1 = sC[(row + 8) * 132 + ucol + 1];
                    float h0 = g0 / (1.f + expf(-g0)) * acc[m][n][2];
                    float h1 = g1 / (1.f + expf(-g1)) * acc[m][n][3];
                    __half b0 = __float2half_rn(h0), b1 = __float2half_rn(h1);
                    uint32_t o = ((uint32_t)p1 * INTER + t * 128 + ucol) >> 1;
                    ((uint32_t*)g_hh)[o] = (uint32_t)*reinterpret_cast<unsigned short*>(&b0) |
                                           ((uint32_t)*reinterpret_cast<unsigned short*>(&b1) << 16);
                }
            }
        }
    }
}

// ================= GEMM2: h(fp16) @ w2(fp16)^T, fp16-acc + fp32 flush, scaled =================
// CTA 128 x 256, K-slab 64, 4-stage, SW128. Stage: Ah[0,16K) Bh[16K,48K). Flush every 2 slabs.
__global__ __launch_bounds__(256, 1) void gemm2_mma() {
    const int e  = blockIdx.z;
    const int M  = g_counts[e];
    const int m0 = blockIdx.y * 128;
    if (m0 >= M) return;
    const int n0 = blockIdx.x * 256;

    extern __shared__ char dsm[];
    int* s_pair = (int*)dsm;
    const uint32_t TILE = smem_u32(dsm) + 1024;

    const int tid = threadIdx.x, wid = tid >> 5, lane = tid & 31;
    const int warp_m = wid >> 2, warp_n = wid & 3;

    if (tid < 128) {
        int gr = m0 + tid;
        s_pair[tid] = (gr < M) ? g_list[e * T_TOK + gr] : -1;
    }
    __syncthreads();

    uint32_t offA[4], dstA[4]; bool vA[4];
    uint32_t offB[8], dstB[8];
    #pragma unroll
    for (int i = 0; i < 4; i++) {
        int c = tid + i * 256, r = c >> 3, cw = c & 7;
        int p = s_pair[r];
        vA[i] = (p >= 0);
        offA[i] = (uint32_t)(vA[i] ? p : 0) * INTER + cw * 8;
        dstA[i] = swz(r * 128 + cw * 16);
    }
    #pragma unroll
    for (int i = 0; i < 8; i++) {
        int c = tid + i * 256, r = c >> 3, cw = c & 7;
        offB[i] = ((uint32_t)e * HID + n0 + r) * INTER + cw * 8;
        dstB[i] = swz(r * 128 + cw * 16);
    }

    auto load_stage = [&](int b, int k0) {
        uint32_t st = TILE + b * STG;
        #pragma unroll
        for (int i = 0; i < 4; i++)
            cp16(st + dstA[i], g_hh + offA[i] + k0, vA[i]);
        #pragma unroll
        for (int i = 0; i < 8; i++)
            cp16(st + 16384 + dstB[i], g_w2h + offB[i] + k0, true);
        cp_commit();
    };

    float acc[4][8][4];
    uint32_t facc[4][8][2];
    #pragma unroll
    for (int m = 0; m < 4; m++)
        #pragma unroll
        for (int n = 0; n < 8; n++) {
            acc[m][n][0] = acc[m][n][1] = acc[m][n][2] = acc[m][n][3] = 0.f;
            facc[m][n][0] = facc[m][n][1] = 0u;
        }

    const uint32_t a_row = warp_m * 64 + (lane & 15);
    const uint32_t a_kb  = (lane >> 4) * 16;
    const uint32_t b_row = warp_n * 64 + (lane & 7) + ((lane >> 4) << 3);
    const uint32_t b_kb  = ((lane >> 3) & 1) * 16;

    const int S = INTER / KSLAB;  // 8
    load_stage(0, 0);
    load_stage(1, KSLAB);
    load_stage(2, 2 * KSLAB);
    for (int s = 0; s < S; s++) {
        if (s + 2 < S) cp_wait<2>(); else if (s + 1 < S) cp_wait<1>(); else cp_wait<0>();
        __syncthreads();
        if (s + 3 < S) load_stage((s + 3) & 3, (s + 3) * KSLAB);
        const uint32_t st = TILE + (s & 3) * STG;
        const uint32_t sAh = st, sBh = st + 16384;
        #pragma unroll
        for (int ks = 0; ks < 4; ks++) {
            uint32_t ah[4][4];
            #pragma unroll
            for (int m = 0; m < 4; m++) {
                uint32_t off = (a_row + m * 16) * 128 + ks * 32 + a_kb;
                ldsm4(ah[m], sAh + swz(off));
            }
            #pragma unroll
            for (int j = 0; j < 4; j++) {
                uint32_t off = (b_row + j * 16) * 128 + ks * 32 + b_kb;
                uint32_t th[4];
                ldsm4(th, sBh + swz(off));
                #pragma unroll
                for (int m = 0; m < 4; m++) {
                    mma_h16(facc[m][2*j],   ah[m], th);
                    mma_h16(facc[m][2*j+1], ah[m], th + 2);
                }
            }
        }
        if (s & 1) flush_acc(facc, acc);
    }

    const int g = lane >> 2, tg = lane & 3;
    #pragma unroll
    for (int m = 0; m < 4; m++) {
        int lr = warp_m * 64 + m * 16 + g;
        int p0 = s_pair[lr], p1 = s_pair[lr + 8];
        float w0 = (p0 >= 0) ? g_pairw[p0] : 0.f;
        float w1 = (p1 >= 0) ? g_pairw[p1] : 0.f;
        #pragma unroll
        for (int n = 0; n < 8; n++) {
            int col = n0 + warp_n * 64 + n * 8 + tg * 2;
            if (p0 >= 0) *(float2*)(g_y + (size_t)p0 * HID + col) = make_float2(w0 * acc[m][n][0], w0 * acc[m][n][1]);
            if (p1 >= 0) *(float2*)(g_y + (size_t)p1 * HID + col) = make_float2(w1 * acc[m][n][2], w1 * acc[m][n][3]);
        }
    }
}

// ---------------- deterministic 8-slot reduction ----------------
__global__ void reduce_kernel(float* __restrict__ out) {
    size_t idx = (size_t)blockIdx.x * blockDim.x + threadIdx.x;
    const size_t total = (size_t)T_TOK * (HID / 4);
    if (idx >= total) return;
    size_t t = idx / (HID / 4);
    int    c = (int)(idx % (HID / 4));
    const float4* base = (const float4*)(g_y + t * (size_t)TOPK * HID) + c;
    float4 s = make_float4(0.f, 0.f, 0.f, 0.f);
    #pragma unroll
    for (int sl = 0; sl < TOPK; sl++) {
        float4 v = base[(size_t)sl * (HID / 4)];
        s.x += v.x; s.y += v.y; s.z += v.z; s.w += v.w;
    }
    ((float4*)out)[idx] = s;
}

extern "C" void kernel_launch(void* const* d_in, const int* in_sizes, int n_in,
                              void* d_out, int out_size) {
    (void)in_sizes; (void)n_in; (void)out_size;
    const float* x   = (const float*)d_in[0];
    const float* gw  = (const float*)d_in[1];
    const float* w13 = (const float*)d_in[2];
    const float* w2  = (const float*)d_in[3];
    float* out = (float*)d_out;

    cudaFuncSetAttribute(gemm1_mma, cudaFuncAttributeMaxDynamicSharedMemorySize, SMEMG);
    cudaFuncSetAttribute(gemm2_mma, cudaFuncAttributeMaxDynamicSharedMemorySize, SMEMG);

    reset_kernel<<<1, 32>>>();
    cvt_x_kernel<<<(T_TOK * HID / 4 + 255) / 256, 256>>>(x);
    cvt_w13_kernel<<<(NEXP * N1 * HID / 4 + 255) / 256, 256>>>(w13);
    cvt_w2_kernel<<<(NEXP * HID * INTER / 4 + 255) / 256, 256>>>(w2);
    router_kernel<<<T_TOK / 8, 256>>>(x, gw);
    gemm1_mma<<<dim3(INTER / 128, 64, NEXP), 256, SMEMG>>>();
    gemm2_mma<<<dim3(HID / 256, 64, NEXP), 256, SMEMG>>>();
    reduce_kernel<<<(int)(((size_t)T_TOK * (HID / 4)) / 256), 256>>>(out);
}

// round 11
// speedup vs baseline: 1.1453x; 1.1453x over previous
#include <cuda_runtime.h>
#include <cuda_fp16.h>
#include <cstdint>

#define T_TOK 8192
#define HID   1536
#define NEXP  32
#define TOPK  8
#define INTER 512
#define N1    (2*INTER)       // 1024
#define MAXP  (T_TOK*TOPK)    // 65536

#define KSLAB 64
#define STG   49152           // Ah16K + Bh32K
#define SMEMG (1024 + 4*STG)  // 197632

// ---------------- device scratch ----------------
__device__ int   g_counts[NEXP];
__device__ int   g_list[NEXP * T_TOK];
__device__ float g_pairw[MAXP];
__device__ __half g_xh[(size_t)T_TOK * HID];
__device__ __half g_w13h[(size_t)NEXP * N1 * HID];
__device__ __half g_w2h[(size_t)NEXP * HID * INTER];
__device__ __half g_hh[(size_t)MAXP * INTER];
__device__ __half g_y[(size_t)MAXP * HID];

// ---------------- PTX helpers (sm_103-baseline safe) ----------------
__device__ __forceinline__ uint32_t smem_u32(const void* p) {
    uint32_t a;
    asm("{ .reg .u64 t; cvta.to.shared.u64 t, %1; cvt.u32.u64 %0, t; }" : "=r"(a) : "l"(p));
    return a;
}
__device__ __forceinline__ uint32_t swz(uint32_t b) { return b ^ ((b >> 3) & 0x70); }

__device__ __forceinline__ void cp16(uint32_t dst, const void* src, bool valid) {
    int sz = valid ? 16 : 0;
    asm volatile("cp.async.cg.shared.global [%0], [%1], 16, %2;\n" :: "r"(dst), "l"(src), "r"(sz));
}
__device__ __forceinline__ void cp_commit() { asm volatile("cp.async.commit_group;" ::: "memory"); }
template <int N> __device__ __forceinline__ void cp_wait() {
    asm volatile("cp.async.wait_group %0;" :: "n"(N) : "memory");
}
__device__ __forceinline__ void ldsm4(uint32_t* r, uint32_t addr) {
    asm volatile("ldmatrix.sync.aligned.m8n8.x4.shared.b16 {%0,%1,%2,%3}, [%4];"
                 : "=r"(r[0]), "=r"(r[1]), "=r"(r[2]), "=r"(r[3]) : "r"(addr));
}
__device__ __forceinline__ void mma_f16(float* c, const uint32_t* a, const uint32_t* b) {
    asm volatile("mma.sync.aligned.m16n8k16.row.col.f32.f16.f16.f32 "
                 "{%0,%1,%2,%3}, {%4,%5,%6,%7}, {%8,%9}, {%0,%1,%2,%3};"
                 : "+f"(c[0]), "+f"(c[1]), "+f"(c[2]), "+f"(c[3])
                 : "r"(a[0]), "r"(a[1]), "r"(a[2]), "r"(a[3]), "r"(b[0]), "r"(b[1]));
}

// ---------------- reset ----------------
__global__ void reset_kernel() {
    if (threadIdx.x < NEXP) g_counts[threadIdx.x] = 0;
}

// ---------------- fp32 -> fp16 (hi only) ----------------
__device__ __forceinline__ void cvt_hi(const float4* __restrict__ src, uint2* __restrict__ hi, int n4) {
    int i = blockIdx.x * blockDim.x + threadIdx.x;
    if (i >= n4) return;
    float4 v = src[i];
    __half h0 = __float2half_rn(v.x), h1 = __float2half_rn(v.y);
    __half h2 = __float2half_rn(v.z), h3 = __float2half_rn(v.w);
    uint2 hv;
    hv.x = (uint32_t)*reinterpret_cast<unsigned short*>(&h0) | ((uint32_t)*reinterpret_cast<unsigned short*>(&h1) << 16);
    hv.y = (uint32_t)*reinterpret_cast<unsigned short*>(&h2) | ((uint32_t)*reinterpret_cast<unsigned short*>(&h3) << 16);
    hi[i] = hv;
}
__global__ void cvt_w13_kernel(const float* __restrict__ w) {
    cvt_hi((const float4*)w, (uint2*)g_w13h, NEXP * N1 * HID / 4);
}
__global__ void cvt_w2_kernel(const float* __restrict__ w) {
    cvt_hi((const float4*)w, (uint2*)g_w2h, NEXP * HID * INTER / 4);
}

// ---------------- Router: one warp per token; x cached in registers; emits fp16 x ----------------
__global__ __launch_bounds__(256) void router_kernel(const float* __restrict__ x,
                                                     const float* __restrict__ gw) {
    const unsigned FULL = 0xffffffffu;
    int warp = (blockIdx.x * blockDim.x + threadIdx.x) >> 5;
    int lane = threadIdx.x & 31;
    if (warp >= T_TOK) return;
    const int t = warp;
    const float4* x4 = (const float4*)(x + (size_t)t * HID);

    // cache the token row: 12 float4 per lane (384 float4 per row)
    float4 xr[12];
    #pragma unroll
    for (int i = 0; i < 12; i++) xr[i] = x4[lane + i * 32];

    // fused cvt_x: emit fp16 copy of x
    uint2* xh2 = (uint2*)(g_xh + (size_t)t * HID);
    #pragma unroll
    for (int i = 0; i < 12; i++) {
        float4 v = xr[i];
        __half h0 = __float2half_rn(v.x), h1 = __float2half_rn(v.y);
        __half h2 = __float2half_rn(v.z), h3 = __float2half_rn(v.w);
        uint2 hv;
        hv.x = (uint32_t)*reinterpret_cast<unsigned short*>(&h0) | ((uint32_t)*reinterpret_cast<unsigned short*>(&h1) << 16);
        hv.y = (uint32_t)*reinterpret_cast<unsigned short*>(&h2) | ((uint32_t)*reinterpret_cast<unsigned short*>(&h3) << 16);
        xh2[lane + i * 32] = hv;
    }

    float logit = 0.f;
    for (int e = 0; e < NEXP; e++) {
        const float4* g4 = (const float4*)(gw + (size_t)e * HID);
        float s = 0.f;
        #pragma unroll
        for (int i = 0; i < 12; i++) {
            float4 b = g4[lane + i * 32];
            s += xr[i].x * b.x + xr[i].y * b.y + xr[i].z * b.z + xr[i].w * b.w;
        }
        #pragma unroll
        for (int off = 16; off; off >>= 1) s += __shfl_xor_sync(FULL, s, off);
        if (lane == e) logit = s;
    }
    float m = logit;
    #pragma unroll
    for (int off = 16; off; off >>= 1) m = fmaxf(m, __shfl_xor_sync(FULL, m, off));
    float p = expf(logit - m);
    float sum = p;
    #pragma unroll
    for (int off = 16; off; off >>= 1) sum += __shfl_xor_sync(FULL, sum, off);
    p = p / sum;

    float keep = p, topsum = 0.f;
    int myslot = -1;
    for (int s = 0; s < TOPK; s++) {
        float v = keep; int bl = lane;
        #pragma unroll
        for (int off = 16; off; off >>= 1) {
            float ov = __shfl_down_sync(FULL, v, off);
            int   ol = __shfl_down_sync(FULL, bl, off);
            if (ov > v || (ov == v && ol < bl)) { v = ov; bl = ol; }
        }
        bl = __shfl_sync(FULL, bl, 0);
        v  = __shfl_sync(FULL, v, 0);
        topsum += v;
        if (lane == bl) { myslot = s; keep = -1.f; }
    }
    if (myslot >= 0) {
        int pos = atomicAdd(&g_counts[lane], 1);
        g_list[lane * T_TOK + pos] = t * TOPK + myslot;
        g_pairw[t * TOPK + myslot] = p / topsum;
    }
}

// ================= GEMM1: x(fp16) @ w13(fp16)^T, single-pass, fused SiLU =================
// CTA 128(M) x 256(N=128 gate + 128 up), K-slab 64, 4-stage, SW128 (128B rows).
__global__ __launch_bounds__(256, 1) void gemm1_mma() {
    const int e  = blockIdx.z;
    const int M  = g_counts[e];
    const int m0 = blockIdx.y * 128;
    if (m0 >= M) return;
    const int t = blockIdx.x;   // 0..3

    extern __shared__ char dsm[];
    int* s_pair = (int*)dsm;
    const uint32_t TILE = smem_u32(dsm) + 1024;
    float* sC = (float*)(dsm + 1024);

    const int tid = threadIdx.x, wid = tid >> 5, lane = tid & 31;
    const int warp_m = wid >> 2, warp_n = wid & 3;

    if (tid < 128) {
        int gr = m0 + tid;
        s_pair[tid] = (gr < M) ? g_list[e * T_TOK + gr] : -1;
    }
    __syncthreads();

    uint32_t offA[4], dstA[4]; bool vA[4];
    uint32_t offB[8], dstB[8];
    #pragma unroll
    for (int i = 0; i < 4; i++) {
        int c = tid + i * 256, r = c >> 3, cw = c & 7;
        int p = s_pair[r];
        vA[i] = (p >= 0);
        offA[i] = (uint32_t)(vA[i] ? (p >> 3) : 0) * HID + cw * 8;
        dstA[i] = swz(r * 128 + cw * 16);
    }
    #pragma unroll
    for (int i = 0; i < 8; i++) {
        int c = tid + i * 256, r = c >> 3, cw = c & 7;
        int brow = (r < 128) ? (t * 128 + r) : (512 + t * 128 + (r - 128));
        offB[i] = ((uint32_t)e * N1 + brow) * HID + cw * 8;
        dstB[i] = swz(r * 128 + cw * 16);
    }

    auto load_stage = [&](int b, int k0) {
        uint32_t st = TILE + b * STG;
        #pragma unroll
        for (int i = 0; i < 4; i++)
            cp16(st + dstA[i], g_xh + offA[i] + k0, vA[i]);
        #pragma unroll
        for (int i = 0; i < 8; i++)
            cp16(st + 16384 + dstB[i], g_w13h + offB[i] + k0, true);
        cp_commit();
    };

    float acc[4][8][4];
    #pragma unroll
    for (int m = 0; m < 4; m++)
        #pragma unroll
        for (int n = 0; n < 8; n++)
            #pragma unroll
            for (int k = 0; k < 4; k++) acc[m][n][k] = 0.f;

    const uint32_t a_row = warp_m * 64 + (lane & 15);
    const uint32_t a_kb  = (lane >> 4) * 16;
    const uint32_t b_row = warp_n * 64 + (lane & 7) + ((lane >> 4) << 3);
    const uint32_t b_kb  = ((lane >> 3) & 1) * 16;

    const int S = HID / KSLAB;  // 24
    load_stage(0, 0);
    load_stage(1, KSLAB);
    load_stage(2, 2 * KSLAB);
    for (int s = 0; s < S; s++) {
        if (s + 2 < S) cp_wait<2>(); else if (s + 1 < S) cp_wait<1>(); else cp_wait<0>();
        __syncthreads();
        if (s + 3 < S) load_stage((s + 3) & 3, (s + 3) * KSLAB);
        const uint32_t st = TILE + (s & 3) * STG;
        const uint32_t sAh = st, sBh = st + 16384;
        #pragma unroll
        for (int ks = 0; ks < 4; ks++) {
            uint32_t ah[4][4];
            #pragma unroll
            for (int m = 0; m < 4; m++) {
                uint32_t off = (a_row + m * 16) * 128 + ks * 32 + a_kb;
                ldsm4(ah[m], sAh + swz(off));
            }
            #pragma unroll
            for (int j = 0; j < 4; j++) {
                uint32_t off = (b_row + j * 16) * 128 + ks * 32 + b_kb;
                uint32_t th[4];
                ldsm4(th, sBh + swz(off));
                #pragma unroll
                for (int m = 0; m < 4; m++) {
                    mma_f16(acc[m][2*j],   ah[m], th);
                    mma_f16(acc[m][2*j+1], ah[m], th + 2);
                }
            }
        }
    }
    __syncthreads();

    // ---- fused epilogue: gate warps (warp_n<2) stage C via smem; up warps emit fp16 h ----
    const int g = lane >> 2, tg = lane & 3;
    if (warp_n < 2) {
        #pragma unroll
        for (int m = 0; m < 4; m++) {
            int row = warp_m * 64 + m * 16 + g;
            #pragma unroll
            for (int n = 0; n < 8; n++) {
                int col = warp_n * 64 + n * 8 + tg * 2;
                sC[row * 132 + col]           = acc[m][n][0];
                sC[row * 132 + col + 1]       = acc[m][n][1];
                sC[(row + 8) * 132 + col]     = acc[m][n][2];
                sC[(row + 8) * 132 + col + 1] = acc[m][n][3];
            }
        }
    }
    __syncthreads();
    if (warp_n >= 2) {
        #pragma unroll
        for (int m = 0; m < 4; m++) {
            int row = warp_m * 64 + m * 16 + g;
            int p0 = s_pair[row], p1 = s_pair[row + 8];
            #pragma unroll
            for (int n = 0; n < 8; n++) {
                int ucol = (warp_n - 2) * 64 + n * 8 + tg * 2;
                if (p0 >= 0) {
                    float g0 = sC[row * 132 + ucol], g1 = sC[row * 132 + ucol + 1];
                    float h0 = g0 / (1.f + expf(-g0)) * acc[m][n][0];
                    float h1 = g1 / (1.f + expf(-g1)) * acc[m][n][1];
                    __half b0 = __float2half_rn(h0), b1 = __float2half_rn(h1);
                    uint32_t o = ((uint32_t)p0 * INTER + t * 128 + ucol) >> 1;
                    ((uint32_t*)g_hh)[o] = (uint32_t)*reinterpret_cast<unsigned short*>(&b0) |
                                           ((uint32_t)*reinterpret_cast<unsigned short*>(&b1) << 16);
                }
                if (p1 >= 0) {
                    float g0 = sC[(row + 8) * 132 + ucol], g1 = sC[(row + 8) * 132 + ucol + 1];
                    float h0 = g0 / (1.f + expf(-g0)) * acc[m][n][2];
                    float h1 = g1 / (1.f + expf(-g1)) * acc[m][n][3];
                    __half b0 = __float2half_rn(h0), b1 = __float2half_rn(h1);
                    uint32_t o = ((uint32_t)p1 * INTER + t * 128 + ucol) >> 1;
                    ((uint32_t*)g_hh)[o] = (uint32_t)*reinterpret_cast<unsigned short*>(&b0) |
                                           ((uint32_t)*reinterpret_cast<unsigned short*>(&b1) << 16);
                }
            }
        }
    }
}

// ================= GEMM2: h(fp16) @ w2(fp16)^T, single-pass, scaled, fp16 y =================
__global__ __launch_bounds__(256, 1) void gemm2_mma() {
    const int e  = blockIdx.z;
    const int M  = g_counts[e];
    const int m0 = blockIdx.y * 128;
    if (m0 >= M) return;
    const int n0 = blockIdx.x * 256;

    extern __shared__ char dsm[];
    int* s_pair = (int*)dsm;
    const uint32_t TILE = smem_u32(dsm) + 1024;

    const int tid = threadIdx.x, wid = tid >> 5, lane = tid & 31;
    const int warp_m = wid >> 2, warp_n = wid & 3;

    if (tid < 128) {
        int gr = m0 + tid;
        s_pair[tid] = (gr < M) ? g_list[e * T_TOK + gr] : -1;
    }
    __syncthreads();

    uint32_t offA[4], dstA[4]; bool vA[4];
    uint32_t offB[8], dstB[8];
    #pragma unroll
    for (int i = 0; i < 4; i++) {
        int c = tid + i * 256, r = c >> 3, cw = c & 7;
        int p = s_pair[r];
        vA[i] = (p >= 0);
        offA[i] = (uint32_t)(vA[i] ? p : 0) * INTER + cw * 8;
        dstA[i] = swz(r * 128 + cw * 16);
    }
    #pragma unroll
    for (int i = 0; i < 8; i++) {
        int c = tid + i * 256, r = c >> 3, cw = c & 7;
        offB[i] = ((uint32_t)e * HID + n0 + r) * INTER + cw * 8;
        dstB[i] = swz(r * 128 + cw * 16);
    }

    auto load_stage = [&](int b, int k0) {
        uint32_t st = TILE + b * STG;
        #pragma unroll
        for (int i = 0; i < 4; i++)
            cp16(st + dstA[i], g_hh + offA[i] + k0, vA[i]);
        #pragma unroll
        for (int i = 0; i < 8; i++)
            cp16(st + 16384 + dstB[i], g_w2h + offB[i] + k0, true);
        cp_commit();
    };

    float acc[4][8][4];
    #pragma unroll
    for (int m = 0; m < 4; m++)
        #pragma unroll
        for (int n = 0; n < 8; n++)
            #pragma unroll
            for (int k = 0; k < 4; k++) acc[m][n][k] = 0.f;

    const uint32_t a_row = warp_m * 64 + (lane & 15);
    const uint32_t a_kb  = (lane >> 4) * 16;
    const uint32_t b_row = warp_n * 64 + (lane & 7) + ((lane >> 4) << 3);
    const uint32_t b_kb  = ((lane >> 3) & 1) * 16;

    const int S = INTER / KSLAB;  // 8
    load_stage(0, 0);
    load_stage(1, KSLAB);
    load_stage(2, 2 * KSLAB);
    for (int s = 0; s < S; s++) {
        if (s + 2 < S) cp_wait<2>(); else if (s + 1 < S) cp_wait<1>(); else cp_wait<0>();
        __syncthreads();
        if (s + 3 < S) load_stage((s + 3) & 3, (s + 3) * KSLAB);
        const uint32_t st = TILE + (s & 3) * STG;
        const uint32_t sAh = st, sBh = st + 16384;
        #pragma unroll
        for (int ks = 0; ks < 4; ks++) {
            uint32_t ah[4][4];
            #pragma unroll
            for (int m = 0; m < 4; m++) {
                uint32_t off = (a_row + m * 16) * 128 + ks * 32 + a_kb;
                ldsm4(ah[m], sAh + swz(off));
            }
            #pragma unroll
            for (int j = 0; j < 4; j++) {
                uint32_t off = (b_row + j * 16) * 128 + ks * 32 + b_kb;
                uint32_t th[4];
                ldsm4(th, sBh + swz(off));
                #pragma unroll
                for (int m = 0; m < 4; m++) {
                    mma_f16(acc[m][2*j],   ah[m], th);
                    mma_f16(acc[m][2*j+1], ah[m], th + 2);
                }
            }
        }
    }

    const int g = lane >> 2, tg = lane & 3;
    #pragma unroll
    for (int m = 0; m < 4; m++) {
        int lr = warp_m * 64 + m * 16 + g;
        int p0 = s_pair[lr], p1 = s_pair[lr + 8];
        float w0 = (p0 >= 0) ? g_pairw[p0] : 0.f;
        float w1 = (p1 >= 0) ? g_pairw[p1] : 0.f;
        #pragma unroll
        for (int n = 0; n < 8; n++) {
            int col = n0 + warp_n * 64 + n * 8 + tg * 2;
            if (p0 >= 0)
                ((__half2*)g_y)[((uint32_t)p0 * HID + col) >> 1] =
                    __floats2half2_rn(w0 * acc[m][n][0], w0 * acc[m][n][1]);
            if (p1 >= 0)
                ((__half2*)g_y)[((uint32_t)p1 * HID + col) >> 1] =
                    __floats2half2_rn(w1 * acc[m][n][2], w1 * acc[m][n][3]);
        }
    }
}

// ---------------- deterministic 8-slot reduction (fp16 in, fp32 out) ----------------
__global__ void reduce_kernel(float* __restrict__ out) {
    size_t idx = (size_t)blockIdx.x * blockDim.x + threadIdx.x;
    const size_t total = (size_t)T_TOK * (HID / 8);
    if (idx >= total) return;
    size_t t = idx / (HID / 8);
    int    c = (int)(idx % (HID / 8));
    const __half* base = g_y + t * (size_t)TOPK * HID + c * 8;
    float s[8] = {0.f, 0.f, 0.f, 0.f, 0.f, 0.f, 0.f, 0.f};
    #pragma unroll
    for (int sl = 0; sl < TOPK; sl++) {
        uint4 v = *(const uint4*)(base + (size_t)sl * HID);
        const __half2* h2 = (const __half2*)&v;
        #pragma unroll
        for (int j = 0; j < 4; j++) {
            float2 f = __half22float2(h2[j]);
            s[2*j]     += f.x;
            s[2*j + 1] += f.y;
        }
    }
    float4* o4 = (float4*)(out + t * HID + c * 8);
    o4[0] = make_float4(s[0], s[1], s[2], s[3]);
    o4[1] = make_float4(s[4], s[5], s[6], s[7]);
}

extern "C" void kernel_launch(void* const* d_in, const int* in_sizes, int n_in,
                              void* d_out, int out_size) {
    (void)in_sizes; (void)n_in; (void)out_size;
    const float* x   = (const float*)d_in[0];
    const float* gw  = (const float*)d_in[1];
    const float* w13 = (const float*)d_in[2];
    const float* w2  = (const float*)d_in[3];
    float* out = (float*)d_out;

    cudaFuncSetAttribute(gemm1_mma, cudaFuncAttributeMaxDynamicSharedMemorySize, SMEMG);
    cudaFuncSetAttribute(gemm2_mma, cudaFuncAttributeMaxDynamicSharedMemorySize, SMEMG);

    reset_kernel<<<1, 32>>>();
    cvt_w13_kernel<<<(NEXP * N1 * HID / 4 + 255) / 256, 256>>>(w13);
    cvt_w2_kernel<<<(NEXP * HID * INTER / 4 + 255) / 256, 256>>>(w2);
    router_kernel<<<T_TOK / 8, 256>>>(x, gw);
    gemm1_mma<<<dim3(INTER / 128, 64, NEXP), 256, SMEMG>>>();
    gemm2_mma<<<dim3(HID / 256, 64, NEXP), 256, SMEMG>>>();
    reduce_kernel<<<(int)(((size_t)T_TOK * (HID / 8)) / 256), 256>>>(out);
}